// round 7
// baseline (speedup 1.0000x reference)
#include <cuda_runtime.h>
#include <cstdint>

// Problem constants.
#define NIN   64
#define NOUT  64
#define HH    192
#define WW    192
#define HO    190
#define WO    190
#define OG    8            // output channels per block
#define NG    (NOUT / OG)  // 8 groups
#define MAXK  2048
#define WCAP  160          // smem-staged weight entries (actual = 128)
#define TROWS 16           // output rows per block
#define TCOLS 96           // output cols per block (6 px per thread x 16 tx)
#define PROWS 18           // patch rows
#define PST   100          // patch row stride in floats (400B, 16B-aligned rows)
#define PBUF  (PROWS * PST)
#define TH    256

typedef unsigned long long ull;

__device__ int g_start[NG * 512 + 1];
__device__ ull g_cnt[NG * 64];            // per (og, in_ch): 8x8-bit ol counts
__device__ __align__(16) ull g_w[MAXK * 10];

__device__ __forceinline__ ull pk2(float lo, float hi) {
    ull r;
    asm("mov.b64 %0, {%1, %2};" : "=l"(r) : "f"(lo), "f"(hi));
    return r;
}
// {a.hi, b.lo} — shifted pair from two adjacent even pairs (<=2 MOVs in SASS).
__device__ __forceinline__ ull shpair(ull a, ull b) {
    ull r;
    asm("{ .reg .f32 x,y,z,w;\n\t"
        "mov.b64 {x,y}, %1;\n\t"
        "mov.b64 {z,w}, %2;\n\t"
        "mov.b64 %0, {y,z}; }"
        : "=l"(r) : "l"(a), "l"(b));
    return r;
}
__device__ __forceinline__ ull fma2(ull a, ull b, ull c) {
    ull d;
    asm("fma.rn.f32x2 %0, %1, %2, %3;" : "=l"(d) : "l"(a), "l"(b), "l"(c));
    return d;
}
__device__ __forceinline__ void cpa16(uint32_t d, const void* s) {
    asm volatile("cp.async.ca.shared.global [%0], [%1], 16;" :: "r"(d), "l"(s));
}
__device__ __forceinline__ void cpcommit() { asm volatile("cp.async.commit_group;"); }
__device__ __forceinline__ void cpwait0()  { asm volatile("cp.async.wait_group 0;"); }

// ---------------------------------------------------------------------------
// Prep (known-correct): CSR over (og, in_ch, ol) bins, duplicated (w,w) f32x2
// weight pairs, plus packed per-(og,in_ch) ol-count u64s.
// ---------------------------------------------------------------------------
__global__ void prep_kernel(const float* __restrict__ w,
                            const int* __restrict__ cin,
                            const int* __restrict__ cout,
                            int K) {
    __shared__ int cnt[4096];
    __shared__ int part[1024];
    int t = threadIdx.x;

    for (int e = t; e < 4096; e += 1024) cnt[e] = 0;
    __syncthreads();

    for (int k = t; k < K; k += 1024) {
        int o = cout[k], i = cin[k];
        int bin = ((o >> 3) << 9) | (i << 3) | (o & 7);
        atomicAdd(&cnt[bin], 1);
    }
    __syncthreads();

    int c4[4];
    int s = 0;
#pragma unroll
    for (int q = 0; q < 4; q++) { c4[q] = cnt[t * 4 + q]; s += c4[q]; }
    part[t] = s;
    __syncthreads();
    for (int off = 1; off < 1024; off <<= 1) {
        int v = (t >= off) ? part[t - off] : 0;
        __syncthreads();
        part[t] += v;
        __syncthreads();
    }
    int run = part[t] - s;
#pragma unroll
    for (int q = 0; q < 4; q++) {
        int bin = t * 4 + q;
        int c = c4[q];
        cnt[bin] = run;
        g_start[bin] = run;
        run += c;
    }
    if (t == 1023) g_start[4096] = run;
    __syncthreads();

    for (int e = t; e < NG * 64; e += 1024) {
        ull v = 0;
#pragma unroll
        for (int q = 0; q < 8; q++) {
            int c = g_start[e * 8 + q + 1] - g_start[e * 8 + q];
            v |= (ull)(unsigned)(c & 255) << (8 * q);
        }
        g_cnt[e] = v;
    }

    for (int k = t; k < K; k += 1024) {
        int o = cout[k], i = cin[k];
        int bin = ((o >> 3) << 9) | (i << 3) | (o & 7);
        int slot = atomicAdd(&cnt[bin], 1);
        if (slot < MAXK) {
            ull* dst = &g_w[(size_t)slot * 10];
#pragma unroll
            for (int q = 0; q < 9; q++) {
                float wv = w[k * 9 + q];
                dst[q] = pk2(wv, wv);
            }
            dst[9] = 0;
        }
    }
}

// ---------------------------------------------------------------------------
// Inner body: 27 FMA2 per entry (3 pixel pairs), 3 chains interleaved.
// Pair p uses E[r][p], O[r][p], E[r][p+1].
// Taps: r0 -> q0.x q0.y q1.x | r1 -> q1.y q2.x q2.y | r2 -> q3.x q3.y w8.
// ---------------------------------------------------------------------------
#define CONV_INNER(WRPTR)                                                     \
    do {                                                                      \
        const ulonglong2* wr = (const ulonglong2*)(WRPTR);                    \
        ulonglong2 q0 = wr[0], q1 = wr[1], q2 = wr[2], q3 = wr[3];            \
        ull w8 = ((const ull*)wr)[8];                                         \
        acc[ol][0] = fma2(E[0][0], q0.x, acc[ol][0]);                         \
        acc[ol][1] = fma2(E[0][1], q0.x, acc[ol][1]);                         \
        acc[ol][2] = fma2(E[0][2], q0.x, acc[ol][2]);                         \
        acc[ol][0] = fma2(O[0][0], q0.y, acc[ol][0]);                         \
        acc[ol][1] = fma2(O[0][1], q0.y, acc[ol][1]);                         \
        acc[ol][2] = fma2(O[0][2], q0.y, acc[ol][2]);                         \
        acc[ol][0] = fma2(E[0][1], q1.x, acc[ol][0]);                         \
        acc[ol][1] = fma2(E[0][2], q1.x, acc[ol][1]);                         \
        acc[ol][2] = fma2(E[0][3], q1.x, acc[ol][2]);                         \
        acc[ol][0] = fma2(E[1][0], q1.y, acc[ol][0]);                         \
        acc[ol][1] = fma2(E[1][1], q1.y, acc[ol][1]);                         \
        acc[ol][2] = fma2(E[1][2], q1.y, acc[ol][2]);                         \
        acc[ol][0] = fma2(O[1][0], q2.x, acc[ol][0]);                         \
        acc[ol][1] = fma2(O[1][1], q2.x, acc[ol][1]);                         \
        acc[ol][2] = fma2(O[1][2], q2.x, acc[ol][2]);                         \
        acc[ol][0] = fma2(E[1][1], q2.y, acc[ol][0]);                         \
        acc[ol][1] = fma2(E[1][2], q2.y, acc[ol][1]);                         \
        acc[ol][2] = fma2(E[1][3], q2.y, acc[ol][2]);                         \
        acc[ol][0] = fma2(E[2][0], q3.x, acc[ol][0]);                         \
        acc[ol][1] = fma2(E[2][1], q3.x, acc[ol][1]);                         \
        acc[ol][2] = fma2(E[2][2], q3.x, acc[ol][2]);                         \
        acc[ol][0] = fma2(O[2][0], q3.y, acc[ol][0]);                         \
        acc[ol][1] = fma2(O[2][1], q3.y, acc[ol][1]);                         \
        acc[ol][2] = fma2(O[2][2], q3.y, acc[ol][2]);                         \
        acc[ol][0] = fma2(E[2][1], w8,   acc[ol][0]);                         \
        acc[ol][1] = fma2(E[2][2], w8,   acc[ol][1]);                         \
        acc[ol][2] = fma2(E[2][3], w8,   acc[ol][2]);                         \
    } while (0)

#define PREFETCH(ch, buf)                                                     \
    do {                                                                      \
        const float* xc = xb + (ch) * (HH * WW);                              \
        uint32_t sb = pbase + (buf) * (PBUF * 4);                             \
        cpa16(sb + sd0, xc + go0);                                            \
        if (has1) cpa16(sb + sd1, xc + go1);                                  \
    } while (0)

// Compute one channel's contribution out of patch buffer `buf`.
#define COMPUTE_CH(ch, buf)                                                   \
    do {                                                                      \
        ull cnts = cw[ch];                                                    \
        const float* pb = &patch[buf][pboff];                                 \
        ull E[3][4], O[3][3];                                                 \
        _Pragma("unroll")                                                     \
        for (int r = 0; r < 3; r++) {                                         \
            const ull* rp = (const ull*)(pb + r * PST);                       \
            E[r][0] = rp[0]; E[r][1] = rp[1];                                 \
            E[r][2] = rp[2]; E[r][3] = rp[3];                                 \
            O[r][0] = shpair(E[r][0], E[r][1]);                               \
            O[r][1] = shpair(E[r][1], E[r][2]);                               \
            O[r][2] = shpair(E[r][2], E[r][3]);                               \
        }                                                                     \
        _Pragma("unroll")                                                     \
        for (int ol = 0; ol < OG; ol++) {                                     \
            int n = (int)(cnts & 255);                                        \
            cnts >>= 8;                                                       \
            while (n--) { CONV_INNER(wp); wp += 10; }                         \
        }                                                                     \
    } while (0)

__global__ __launch_bounds__(TH, 2)
void conv_kernel(const float* __restrict__ x,
                 const float* __restrict__ bias,
                 float* __restrict__ out) {
    __shared__ __align__(16) float patch[4][PBUF];     // 28.8 KB
    __shared__ __align__(16) ull ws[WCAP * 10];        // 12.8 KB
    __shared__ ull cw[64];
    __shared__ unsigned umask[2];
    __shared__ unsigned char chlist[64];
    __shared__ int chn_s;

    int bz = blockIdx.z;
    int b = bz >> 3, og = bz & 7;
    int h0 = blockIdx.y * TROWS;
    int w0  = blockIdx.x ? (WO - TCOLS) : 0;   // 0 or 94 (2-col overlap, benign)
    int w0a = w0 & ~3;                         // 16B-aligned patch origin
    int xoff = w0 - w0a;                       // 0 or 2
    int t = threadIdx.x, ty = t >> 4, tx = t & 15;

    // Stage packed counts; ballots for used channels (warps 0,1 whole).
    if (t < 64) {
        ull c = g_cnt[(og << 6) + t];
        cw[t] = c;
        unsigned mm = __ballot_sync(0xFFFFFFFFu, c != 0);
        if ((t & 31) == 0) umask[t >> 5] = mm;
    }

    int jb = g_start[og << 9];
    int nE = g_start[(og << 9) + 512] - jb;
    int nStage = nE < WCAP ? nE : WCAP;
    for (int e = t; e < nStage * 10; e += TH) ws[e] = g_w[(size_t)jb * 10 + e];

    ull acc[OG][3];
#pragma unroll
    for (int ol = 0; ol < OG; ol++) {
        float bv = bias[og * OG + ol];
        acc[ol][0] = pk2(bv, bv);
        acc[ol][1] = acc[ol][0];
        acc[ol][2] = acc[ol][0];
    }
    __syncthreads();

    // Build compact used-channel list via ballot prefix.
    if (t < 64) {
        unsigned mm = (t < 32) ? umask[0] : umask[1];
        int lane = t & 31;
        int pos = __popc(mm & ((1u << lane) - 1)) +
                  ((t >= 32) ? __popc(umask[0]) : 0);
        if (cw[t] != 0) chlist[pos] = (unsigned char)t;
    }
    if (t == 0) chn_s = __popc(umask[0]) + __popc(umask[1]);

    uint32_t pbase = (uint32_t)__cvta_generic_to_shared(&patch[0][0]);
    const float* xb = x + (size_t)b * NIN * HH * WW;

    // Hoisted loader addressing: 18 rows x 25 chunks of 16B = 450 slots over
    // 256 threads (threads t<194 take a second slot).
    int r0 = t / 25, c0 = (t - r0 * 25) * 4;
    int ih0 = h0 + r0; if (ih0 > HH - 1) ih0 = HH - 1;
    int go0 = ih0 * WW + w0a + c0;
    uint32_t sd0 = (uint32_t)(r0 * PST + c0) * 4;
    int s2 = t + TH;
    bool has1 = s2 < PROWS * 25;
    int r1 = s2 / 25, c1 = (s2 - r1 * 25) * 4;
    int ih1 = h0 + r1; if (ih1 > HH - 1) ih1 = HH - 1;
    int go1 = ih1 * WW + w0a + c1;
    uint32_t sd1 = (uint32_t)(r1 * PST + c1) * 4;
    int pboff = ty * PST + xoff + tx * 6;

    __syncthreads();                // chlist/chn_s visible
    int chn = chn_s;

    // Pipelined pair loop: one wait+barrier per TWO channels (4 buffers).
    {
        const ull* wp = (nE <= WCAP) ? ws : &g_w[(size_t)jb * 10];
        // Prologue: prefetch pair 0 into bufs {0,1}.
        if (chn > 0) PREFETCH(chlist[0], 0);
        if (chn > 1) PREFETCH(chlist[1], 1);
        cpcommit();

        int npair = (chn + 1) >> 1;
        for (int p = 0; p < npair; ++p) {
            int base = 2 * p;
            int bufa = (p & 1) << 1;       // 0 or 2
            cpwait0();
            __syncthreads();
            // Prefetch next pair into the other two buffers.
            int nb = bufa ^ 2;
            if (base + 2 < chn) PREFETCH(chlist[base + 2], nb);
            if (base + 3 < chn) PREFETCH(chlist[base + 3], nb + 1);
            cpcommit();

            { int ch = chlist[base]; COMPUTE_CH(ch, bufa); }
            if (base + 1 < chn) { int ch = chlist[base + 1]; COMPUTE_CH(ch, bufa + 1); }
        }
    }

    // Store: 3 full float2 per ol (all 8B aligned; no partial px in-tile).
    int h = h0 + ty;
    if (h < HO) {
        int wb = w0 + tx * 6;
        float* ob = out + (((size_t)(b * NOUT + og * OG)) * HO + h) * WO + wb;
#pragma unroll
        for (int ol = 0; ol < OG; ol++) {
            float2 v0, v1, v2;
            asm("mov.b64 {%0, %1}, %2;" : "=f"(v0.x), "=f"(v0.y) : "l"(acc[ol][0]));
            asm("mov.b64 {%0, %1}, %2;" : "=f"(v1.x), "=f"(v1.y) : "l"(acc[ol][1]));
            asm("mov.b64 {%0, %1}, %2;" : "=f"(v2.x), "=f"(v2.y) : "l"(acc[ol][2]));
            float* p = ob + (size_t)ol * HO * WO;
            *(float2*)p = v0;
            *(float2*)(p + 2) = v1;
            *(float2*)(p + 4) = v2;
        }
    }
}

// ---------------------------------------------------------------------------
extern "C" void kernel_launch(void* const* d_in, const int* in_sizes, int n_in,
                              void* d_out, int out_size) {
    const float* x    = (const float*)d_in[0];
    const float* w    = (const float*)d_in[1];
    const float* bias = (const float*)d_in[2];
    const int*   cin  = (const int*)d_in[3];
    const int*   cout = (const int*)d_in[4];
    int K = in_sizes[3];                       // 1024
    int B = in_sizes[0] / (NIN * HH * WW);     // 4

    prep_kernel<<<1, 1024>>>(w, cin, cout, K);

    dim3 grid(2, (HO + TROWS - 1) / TROWS, B * NG);   // (2, 12, 32)
    conv_kernel<<<grid, TH>>>(x, bias, (float*)d_out);
}

// round 8
// speedup vs baseline: 1.0830x; 1.0830x over previous
#include <cuda_runtime.h>
#include <cstdint>

// Problem constants.
#define NIN   64
#define NOUT  64
#define HH    192
#define WW    192
#define HO    190
#define WO    190
#define OG    8            // output channels per block
#define NG    (NOUT / OG)  // 8 groups
#define MAXK  2048
#define WCAP  160          // smem-staged weight entries (actual = 128)
#define TROWS 20           // output rows per block
#define TCOLS 96           // output cols per block (6 px per thread x 16 tx)
#define PROWS 22           // patch rows
#define PST   100          // patch row stride in floats (400B, 16B-aligned rows)
#define PBUF  (PROWS * PST)
#define TH    320

typedef unsigned long long ull;

__device__ int g_start[NG * 512 + 1];
__device__ ull g_cnt[NG * 64];            // per (og, in_ch): 8x8-bit ol counts
__device__ __align__(16) ull g_w[MAXK * 10];

__device__ __forceinline__ ull pk2(float lo, float hi) {
    ull r;
    asm("mov.b64 %0, {%1, %2};" : "=l"(r) : "f"(lo), "f"(hi));
    return r;
}
// {a.hi, b.lo} — shifted pair from two adjacent even pairs.
__device__ __forceinline__ ull shpair(ull a, ull b) {
    ull r;
    asm("{ .reg .f32 x,y,z,w;\n\t"
        "mov.b64 {x,y}, %1;\n\t"
        "mov.b64 {z,w}, %2;\n\t"
        "mov.b64 %0, {y,z}; }"
        : "=l"(r) : "l"(a), "l"(b));
    return r;
}
__device__ __forceinline__ ull fma2(ull a, ull b, ull c) {
    ull d;
    asm("fma.rn.f32x2 %0, %1, %2, %3;" : "=l"(d) : "l"(a), "l"(b), "l"(c));
    return d;
}
__device__ __forceinline__ void cpa16(uint32_t d, const void* s) {
    asm volatile("cp.async.ca.shared.global [%0], [%1], 16;" :: "r"(d), "l"(s));
}
__device__ __forceinline__ void cpcommit() { asm volatile("cp.async.commit_group;"); }
__device__ __forceinline__ void cpwait0()  { asm volatile("cp.async.wait_group 0;"); }

// ---------------------------------------------------------------------------
// Prep (known-correct): CSR over (og, in_ch, ol) bins, duplicated (w,w) f32x2
// weight pairs, plus packed per-(og,in_ch) ol-count u64s.
// ---------------------------------------------------------------------------
__global__ void prep_kernel(const float* __restrict__ w,
                            const int* __restrict__ cin,
                            const int* __restrict__ cout,
                            int K) {
    __shared__ int cnt[4096];
    __shared__ int part[1024];
    int t = threadIdx.x;

    for (int e = t; e < 4096; e += 1024) cnt[e] = 0;
    __syncthreads();

    for (int k = t; k < K; k += 1024) {
        int o = cout[k], i = cin[k];
        int bin = ((o >> 3) << 9) | (i << 3) | (o & 7);
        atomicAdd(&cnt[bin], 1);
    }
    __syncthreads();

    int c4[4];
    int s = 0;
#pragma unroll
    for (int q = 0; q < 4; q++) { c4[q] = cnt[t * 4 + q]; s += c4[q]; }
    part[t] = s;
    __syncthreads();
    for (int off = 1; off < 1024; off <<= 1) {
        int v = (t >= off) ? part[t - off] : 0;
        __syncthreads();
        part[t] += v;
        __syncthreads();
    }
    int run = part[t] - s;
#pragma unroll
    for (int q = 0; q < 4; q++) {
        int bin = t * 4 + q;
        int c = c4[q];
        cnt[bin] = run;
        g_start[bin] = run;
        run += c;
    }
    if (t == 1023) g_start[4096] = run;
    __syncthreads();

    for (int e = t; e < NG * 64; e += 1024) {
        ull v = 0;
#pragma unroll
        for (int q = 0; q < 8; q++) {
            int c = g_start[e * 8 + q + 1] - g_start[e * 8 + q];
            v |= (ull)(unsigned)(c & 255) << (8 * q);
        }
        g_cnt[e] = v;
    }

    for (int k = t; k < K; k += 1024) {
        int o = cout[k], i = cin[k];
        int bin = ((o >> 3) << 9) | (i << 3) | (o & 7);
        int slot = atomicAdd(&cnt[bin], 1);
        if (slot < MAXK) {
            ull* dst = &g_w[(size_t)slot * 10];
#pragma unroll
            for (int q = 0; q < 9; q++) {
                float wv = w[k * 9 + q];
                dst[q] = pk2(wv, wv);
            }
            dst[9] = 0;
        }
    }
}

// ---------------------------------------------------------------------------
// Inner body: 27 FMA2 per entry (3 pixel pairs), 3 chains interleaved.
// Pair p uses E[r][p], O[r][p], E[r][p+1].
// Taps: r0 -> q0.x q0.y q1.x | r1 -> q1.y q2.x q2.y | r2 -> q3.x q3.y w8.
// ---------------------------------------------------------------------------
#define CONV_INNER(WRPTR)                                                     \
    do {                                                                      \
        const ulonglong2* wr = (const ulonglong2*)(WRPTR);                    \
        ulonglong2 q0 = wr[0], q1 = wr[1], q2 = wr[2], q3 = wr[3];            \
        ull w8 = ((const ull*)wr)[8];                                         \
        acc[ol][0] = fma2(E[0][0], q0.x, acc[ol][0]);                         \
        acc[ol][1] = fma2(E[0][1], q0.x, acc[ol][1]);                         \
        acc[ol][2] = fma2(E[0][2], q0.x, acc[ol][2]);                         \
        acc[ol][0] = fma2(O[0][0], q0.y, acc[ol][0]);                         \
        acc[ol][1] = fma2(O[0][1], q0.y, acc[ol][1]);                         \
        acc[ol][2] = fma2(O[0][2], q0.y, acc[ol][2]);                         \
        acc[ol][0] = fma2(E[0][1], q1.x, acc[ol][0]);                         \
        acc[ol][1] = fma2(E[0][2], q1.x, acc[ol][1]);                         \
        acc[ol][2] = fma2(E[0][3], q1.x, acc[ol][2]);                         \
        acc[ol][0] = fma2(E[1][0], q1.y, acc[ol][0]);                         \
        acc[ol][1] = fma2(E[1][1], q1.y, acc[ol][1]);                         \
        acc[ol][2] = fma2(E[1][2], q1.y, acc[ol][2]);                         \
        acc[ol][0] = fma2(O[1][0], q2.x, acc[ol][0]);                         \
        acc[ol][1] = fma2(O[1][1], q2.x, acc[ol][1]);                         \
        acc[ol][2] = fma2(O[1][2], q2.x, acc[ol][2]);                         \
        acc[ol][0] = fma2(E[1][1], q2.y, acc[ol][0]);                         \
        acc[ol][1] = fma2(E[1][2], q2.y, acc[ol][1]);                         \
        acc[ol][2] = fma2(E[1][3], q2.y, acc[ol][2]);                         \
        acc[ol][0] = fma2(E[2][0], q3.x, acc[ol][0]);                         \
        acc[ol][1] = fma2(E[2][1], q3.x, acc[ol][1]);                         \
        acc[ol][2] = fma2(E[2][2], q3.x, acc[ol][2]);                         \
        acc[ol][0] = fma2(O[2][0], q3.y, acc[ol][0]);                         \
        acc[ol][1] = fma2(O[2][1], q3.y, acc[ol][1]);                         \
        acc[ol][2] = fma2(O[2][2], q3.y, acc[ol][2]);                         \
        acc[ol][0] = fma2(E[2][1], w8,   acc[ol][0]);                         \
        acc[ol][1] = fma2(E[2][2], w8,   acc[ol][1]);                         \
        acc[ol][2] = fma2(E[2][3], w8,   acc[ol][2]);                         \
    } while (0)

#define PREFETCH(ch, buf)                                                     \
    do {                                                                      \
        const float* xc = xb + (ch) * (HH * WW);                              \
        uint32_t sb = pbase + (buf) * (PBUF * 4);                             \
        cpa16(sb + sd0, xc + go0);                                            \
        if (has1) cpa16(sb + sd1, xc + go1);                                  \
    } while (0)

__global__ __launch_bounds__(TH, 2)
void conv_kernel(const float* __restrict__ x,
                 const float* __restrict__ bias,
                 float* __restrict__ out) {
    __shared__ __align__(16) float patch[2][PBUF];     // 17.6 KB
    __shared__ __align__(16) ull ws[WCAP * 10];        // 12.8 KB
    __shared__ ull cw[64];
    __shared__ unsigned umask[2];

    int bz = blockIdx.z;
    int b = bz >> 3, og = bz & 7;
    int h0 = blockIdx.y * TROWS;
    int w0  = blockIdx.x ? (WO - TCOLS) : 0;   // 0 or 94 (2-col overlap, benign)
    int w0a = w0 & ~3;                         // 16B-aligned patch origin
    int xoff = w0 - w0a;                       // 0 or 2
    int t = threadIdx.x, ty = t >> 4, tx = t & 15;

    // Stage packed counts; ballots for used channels (warps 0,1 whole).
    if (t < 64) {
        ull c = g_cnt[(og << 6) + t];
        cw[t] = c;
        unsigned mm = __ballot_sync(0xFFFFFFFFu, c != 0);
        if ((t & 31) == 0) umask[t >> 5] = mm;
    }

    int jb = g_start[og << 9];
    int nE = g_start[(og << 9) + 512] - jb;
    int nStage = nE < WCAP ? nE : WCAP;
    for (int e = t; e < nStage * 10; e += TH) ws[e] = g_w[(size_t)jb * 10 + e];

    ull acc[OG][3];
#pragma unroll
    for (int ol = 0; ol < OG; ol++) {
        float bv = bias[og * OG + ol];
        acc[ol][0] = pk2(bv, bv);
        acc[ol][1] = acc[ol][0];
        acc[ol][2] = acc[ol][0];
    }
    __syncthreads();

    ull mask = (ull)umask[0] | ((ull)umask[1] << 32);
    uint32_t pbase = (uint32_t)__cvta_generic_to_shared(&patch[0][0]);
    const float* xb = x + (size_t)b * NIN * HH * WW;

    // Hoisted loader addressing: 22 rows x 25 chunks of 16B = 550 slots over
    // 320 threads (threads t<230 take a second slot).
    int r0 = t / 25, c0 = (t - r0 * 25) * 4;
    int ih0 = h0 + r0; if (ih0 > HH - 1) ih0 = HH - 1;
    int go0 = ih0 * WW + w0a + c0;
    uint32_t sd0 = (uint32_t)(r0 * PST + c0) * 4;
    int s2 = t + TH;
    bool has1 = s2 < PROWS * 25;               // t < 230
    int r1 = s2 / 25, c1 = (s2 - r1 * 25) * 4;
    int ih1 = h0 + r1; if (ih1 > HH - 1) ih1 = HH - 1;
    int go1 = ih1 * WW + w0a + c1;
    uint32_t sd1 = (uint32_t)(r1 * PST + c1) * 4;
    int pboff = ty * PST + xoff + tx * 6;

    // Pipelined channel loop: prefetch next patch while computing current.
    {
        const ull* wp = (nE <= WCAP) ? ws : &g_w[(size_t)jb * 10];
        ull m = mask;
        int i = m ? (__ffsll((long long)m) - 1) : -1;
        m &= m - 1;
        if (i >= 0) PREFETCH(i, 0);
        cpcommit();
        int cur = 0;
        while (i >= 0) {
            int nx = m ? (__ffsll((long long)m) - 1) : -1;
            m &= m - 1;
            cpwait0();
            __syncthreads();
            if (nx >= 0) PREFETCH(nx, cur ^ 1);
            cpcommit();

            // E pairs: direct 8B-aligned LDS.64 results; O pairs: 3 shpair/row.
            const float* pb = &patch[cur][pboff];
            ull E[3][4], O[3][3];
#pragma unroll
            for (int r = 0; r < 3; r++) {
                const ull* rp = (const ull*)(pb + r * PST);
                E[r][0] = rp[0]; E[r][1] = rp[1];
                E[r][2] = rp[2]; E[r][3] = rp[3];
                O[r][0] = shpair(E[r][0], E[r][1]);
                O[r][1] = shpair(E[r][1], E[r][2]);
                O[r][2] = shpair(E[r][2], E[r][3]);
            }

            ull cnts = cw[i];
#pragma unroll
            for (int ol = 0; ol < OG; ol++) {
                int n = (int)(cnts & 255);
                cnts >>= 8;
                while (n--) { CONV_INNER(wp); wp += 10; }
            }
            cur ^= 1;
            i = nx;
        }
    }

    // Store: 3 full float2 per ol (all 8B aligned; no partial px in-tile).
    int h = h0 + ty;
    if (h < HO) {
        int wb = w0 + tx * 6;
        float* ob = out + (((size_t)(b * NOUT + og * OG)) * HO + h) * WO + wb;
#pragma unroll
        for (int ol = 0; ol < OG; ol++) {
            float2 v0, v1, v2;
            asm("mov.b64 {%0, %1}, %2;" : "=f"(v0.x), "=f"(v0.y) : "l"(acc[ol][0]));
            asm("mov.b64 {%0, %1}, %2;" : "=f"(v1.x), "=f"(v1.y) : "l"(acc[ol][1]));
            asm("mov.b64 {%0, %1}, %2;" : "=f"(v2.x), "=f"(v2.y) : "l"(acc[ol][2]));
            float* p = ob + (size_t)ol * HO * WO;
            *(float2*)p = v0;
            *(float2*)(p + 2) = v1;
            *(float2*)(p + 4) = v2;
        }
    }
}

// ---------------------------------------------------------------------------
extern "C" void kernel_launch(void* const* d_in, const int* in_sizes, int n_in,
                              void* d_out, int out_size) {
    const float* x    = (const float*)d_in[0];
    const float* w    = (const float*)d_in[1];
    const float* bias = (const float*)d_in[2];
    const int*   cin  = (const int*)d_in[3];
    const int*   cout = (const int*)d_in[4];
    int K = in_sizes[3];                       // 1024
    int B = in_sizes[0] / (NIN * HH * WW);     // 4

    prep_kernel<<<1, 1024>>>(w, cin, cout, K);

    dim3 grid(2, (HO + TROWS - 1) / TROWS, B * NG);   // (2, 10, 32)
    conv_kernel<<<grid, TH>>>(x, bias, (float*)d_out);
}